// round 5
// baseline (speedup 1.0000x reference)
#include <cuda_runtime.h>
#include <cstdint>
#include <math.h>

#define T_SEQ 2048
#define DMODEL 2048
#define NH 32
#define NKV 8
#define HD 64

// Scratch (device globals: allocation-free per harness rules)
__device__ float g_q[(size_t)2 * NH * T_SEQ * HD];    // (b, h, t, d)
__device__ float g_ctx[(size_t)2 * T_SEQ * NH * HD];  // (b, t, h, d)

__device__ __forceinline__ uint32_t f2tf32(float f) {
    uint32_t u;
    asm("cvt.rna.tf32.f32 %0, %1;" : "=r"(u) : "f"(f));
    return u;
}

__device__ __forceinline__ void mma_tf32(float* c, uint32_t a0, uint32_t a1,
                                         uint32_t a2, uint32_t a3,
                                         uint32_t b0, uint32_t b1) {
    asm volatile(
        "mma.sync.aligned.m16n8k8.row.col.f32.tf32.tf32.f32 "
        "{%0,%1,%2,%3}, {%4,%5,%6,%7}, {%8,%9}, {%0,%1,%2,%3};"
        : "+f"(c[0]), "+f"(c[1]), "+f"(c[2]), "+f"(c[3])
        : "r"(a0), "r"(a1), "r"(a2), "r"(a3), "r"(b0), "r"(b1));
}

__device__ __forceinline__ int kperm(int j) { return ((j & 3) << 1) | (j >> 2); }

// ============================================================================
// Double-buffered tf32 mma.sync GEMM, 128x128 tile, BK=32, 8 warps (2x4).
// KIND 0: fused QKV projections. blockIdx.x: [0,16) Q+RoPE->g_q,
//         [16,20) K+RoPE->kout, [20,24) V->vout.
// KIND 1: output projection, A := g_ctx, C := out.
// One __syncthreads per K-stage; LDG issued before MMA; STS into other buffer.
// ============================================================================
#define SPAD 40
#define TILE_W (128 * SPAD)   // words per operand tile

template <int KIND>
__global__ __launch_bounds__(256) void db_gemm(
    const float* __restrict__ x,
    const float* __restrict__ wq, const float* __restrict__ bq,
    const float* __restrict__ wk, const float* __restrict__ bk,
    const float* __restrict__ wv, const float* __restrict__ bv,
    float* __restrict__ kout, float* __restrict__ vout,
    float* __restrict__ outC,
    const float* __restrict__ cosT, const float* __restrict__ sinT)
{
    extern __shared__ __align__(16) uint32_t sm[];
    uint32_t* As = sm;               // [2][TILE_W]
    uint32_t* Bs = sm + 2 * TILE_W;  // [2][TILE_W]

    const int tid = threadIdx.x;
    const int wid = tid >> 5;
    const int lane = tid & 31;
    const int gr = lane >> 2;
    const int tig = lane & 3;
    const int wm = wid >> 2;
    const int wn = wid & 3;

    constexpr int K = DMODEL;
    const int m0 = blockIdx.y * 128;

    int mode, n0;
    const float* A;
    const float* W;
    const float* bias;
    if (KIND == 1) {
        mode = 0; n0 = blockIdx.x * 128; A = g_ctx; W = wq; bias = bq;
    } else {
        const int bx = blockIdx.x;
        A = x;
        if (bx < 16)      { mode = 1; n0 = bx * 128;        W = wq; bias = bq; }
        else if (bx < 20) { mode = 2; n0 = (bx - 16) * 128; W = wk; bias = bk; }
        else              { mode = 3; n0 = (bx - 20) * 128; W = wv; bias = bv; }
    }

    const int rbase = tid >> 3;
    const int cg = tid & 7;
    const float* Arow[4];
    const float* Wrow[4];
    uint32_t soff[4];
#pragma unroll
    for (int i = 0; i < 4; i++) {
        Arow[i] = A + (size_t)(m0 + i * 32 + rbase) * K + cg * 4;
        Wrow[i] = W + (size_t)(n0 + i * 32 + rbase) * K + cg * 4;
        soff[i] = (uint32_t)((i * 32 + rbase) * SPAD + cg * 4);
    }

    float4 pa[4], pb[4];
#pragma unroll
    for (int i = 0; i < 4; i++) {
        pa[i] = *(const float4*)Arow[i];
        pb[i] = *(const float4*)Wrow[i];
    }

    float acc[4][4][4];
#pragma unroll
    for (int mi = 0; mi < 4; mi++)
#pragma unroll
        for (int ni = 0; ni < 4; ni++)
#pragma unroll
            for (int r = 0; r < 4; r++) acc[mi][ni][r] = 0.f;

    // Prologue: stage 0 into buffer 0
#pragma unroll
    for (int i = 0; i < 4; i++) {
        uint4 ua, ub;
        ua.x = f2tf32(pa[i].x); ua.y = f2tf32(pa[i].y);
        ua.z = f2tf32(pa[i].z); ua.w = f2tf32(pa[i].w);
        ub.x = f2tf32(pb[i].x); ub.y = f2tf32(pb[i].y);
        ub.z = f2tf32(pb[i].z); ub.w = f2tf32(pb[i].w);
        *(uint4*)&As[soff[i]] = ua;
        *(uint4*)&Bs[soff[i]] = ub;
    }
    __syncthreads();

    const int NST = K / 32;
    for (int s = 0; s < NST; s++) {
        const uint32_t bo = (uint32_t)(s & 1) * TILE_W;
        const uint32_t* Abase = As + bo + (wm * 64) * SPAD;
        const uint32_t* Bbase = Bs + bo + (wn * 32) * SPAD;

        if (s + 1 < NST) {
#pragma unroll
            for (int i = 0; i < 4; i++) {
                Arow[i] += 32;
                Wrow[i] += 32;
                pa[i] = *(const float4*)Arow[i];
                pb[i] = *(const float4*)Wrow[i];
            }
        }

#pragma unroll
        for (int kk = 0; kk < 4; kk++) {
            const int kc = kk * 8 + 2 * tig;
            uint32_t bf[4][2];
#pragma unroll
            for (int ni = 0; ni < 4; ni++) {
                uint64_t bv = *(const uint64_t*)&Bbase[(ni * 8 + gr) * SPAD + kc];
                bf[ni][0] = (uint32_t)bv;
                bf[ni][1] = (uint32_t)(bv >> 32);
            }
#pragma unroll
            for (int mi = 0; mi < 4; mi++) {
                uint64_t a02 = *(const uint64_t*)&Abase[(mi * 16 + gr) * SPAD + kc];
                uint64_t a13 = *(const uint64_t*)&Abase[(mi * 16 + gr + 8) * SPAD + kc];
                uint32_t a0 = (uint32_t)a02, a2 = (uint32_t)(a02 >> 32);
                uint32_t a1 = (uint32_t)a13, a3 = (uint32_t)(a13 >> 32);
#pragma unroll
                for (int ni = 0; ni < 4; ni++)
                    mma_tf32(acc[mi][ni], a0, a1, a2, a3, bf[ni][0], bf[ni][1]);
            }
        }

        if (s + 1 < NST) {
            const uint32_t nbo = (uint32_t)((s + 1) & 1) * TILE_W;
#pragma unroll
            for (int i = 0; i < 4; i++) {
                uint4 ua, ub;
                ua.x = f2tf32(pa[i].x); ua.y = f2tf32(pa[i].y);
                ua.z = f2tf32(pa[i].z); ua.w = f2tf32(pa[i].w);
                ub.x = f2tf32(pb[i].x); ub.y = f2tf32(pb[i].y);
                ub.z = f2tf32(pb[i].z); ub.w = f2tf32(pb[i].w);
                *(uint4*)&As[nbo + soff[i]] = ua;
                *(uint4*)&Bs[nbo + soff[i]] = ub;
            }
            __syncthreads();
        }
    }

    // ---------------- Register epilogue ----------------
#pragma unroll
    for (int mi = 0; mi < 4; mi++) {
#pragma unroll
        for (int half = 0; half < 2; half++) {
            const int m = m0 + wm * 64 + mi * 16 + gr + half * 8;
            const int bb = m >> 11;
            const int t = m & (T_SEQ - 1);
#pragma unroll
            for (int ni = 0; ni < 4; ni++) {
                const int n = n0 + wn * 32 + ni * 8 + tig * 2;
                float v0 = acc[mi][ni][half * 2 + 0] + bias[n];
                float v1 = acc[mi][ni][half * 2 + 1] + bias[n + 1];
                if (mode == 1 || mode == 2) {
                    const int hh = (n & 63) >> 1;
                    const float c = cosT[t * (HD / 2) + hh];
                    const float ss = sinT[t * (HD / 2) + hh];
                    const float e = v0 * c - v1 * ss;
                    const float o = v0 * ss + v1 * c;
                    v0 = e;
                    v1 = o;
                }
                float2 wv2 = make_float2(v0, v1);
                if (mode == 0) {
                    *(float2*)&outC[(size_t)m * DMODEL + n] = wv2;
                } else if (mode == 1) {
                    *(float2*)&g_q[(((size_t)(bb * NH + (n >> 6))) * T_SEQ + t) * HD + (n & 63)] = wv2;
                } else {
                    float* dst = (mode == 2) ? kout : vout;
                    *(float2*)&dst[(((size_t)(bb * NKV + (n >> 6))) * T_SEQ + t) * HD + (n & 63)] = wv2;
                }
            }
        }
    }
}

// ============================================================================
// Flash attention with tf32 mma.sync (unchanged from R4, passing).
// ============================================================================
#define PKS 68
#define PVT 72

__global__ __launch_bounds__(256) void attn_mma(const float* __restrict__ Kg,
                                                const float* __restrict__ Vg)
{
    __shared__ __align__(16) uint32_t Ks[64 * PKS];
    __shared__ __align__(16) uint32_t Vt[64 * PVT];

    const int tid = threadIdx.x;
    const int wid = tid >> 5;
    const int lane = tid & 31;
    const int gr = lane >> 2;
    const int tig = lane & 3;

    const int qt = blockIdx.x;
    const int bh = blockIdx.y;
    const int b = bh >> 5;
    const int h = bh & 31;
    const int kvh = h >> 2;

    const float* Qg = g_q + (((size_t)(b * NH + h)) * T_SEQ + qt * 128 + wid * 16) * HD;
    uint32_t qa[8][4];
#pragma unroll
    for (int ks = 0; ks < 8; ks++) {
        qa[ks][0] = f2tf32(Qg[gr * HD + 8 * ks + tig] * 0.125f);
        qa[ks][1] = f2tf32(Qg[(gr + 8) * HD + 8 * ks + tig] * 0.125f);
        qa[ks][2] = f2tf32(Qg[gr * HD + 8 * ks + tig + 4] * 0.125f);
        qa[ks][3] = f2tf32(Qg[(gr + 8) * HD + 8 * ks + tig + 4] * 0.125f);
    }

    const float* Kb = Kg + ((size_t)(b * NKV + kvh)) * T_SEQ * HD;
    const float* Vb = Vg + ((size_t)(b * NKV + kvh)) * T_SEQ * HD;

    float ctx[8][4];
#pragma unroll
    for (int ni = 0; ni < 8; ni++)
#pragma unroll
        for (int r = 0; r < 4; r++) ctx[ni][r] = 0.f;
    float mrun0 = -INFINITY, mrun1 = -INFINITY;
    float lrun0 = 0.f, lrun1 = 0.f;

    const int lkey = tid >> 2;
    const int ldseg = (tid & 3) * 16;
    const int vkey = tid & 63;
    const int vds = (tid >> 6) * 16;
    const int vpk = ((vkey >> 3) << 3) | kperm(vkey & 7);

    const int row0 = qt * 128 + wid * 16 + gr;
    const int row1 = row0 + 8;

    const int njt = 2 * qt + 2;
    for (int jt = 0; jt < njt; jt++) {
        __syncthreads();
        const float* Kp = Kb + (size_t)jt * 64 * HD;
        const float* Vp = Vb + (size_t)jt * 64 * HD;
#pragma unroll
        for (int c = 0; c < 4; c++) {
            const int d0 = ldseg + 4 * c;
            float4 v = *(const float4*)&Kp[lkey * HD + d0];
            const int blk = (d0 >> 3) << 3;
            const int j0 = d0 & 7;
            uint32_t* kr = &Ks[lkey * PKS + blk];
            kr[kperm(j0 + 0)] = f2tf32(v.x);
            kr[kperm(j0 + 1)] = f2tf32(v.y);
            kr[kperm(j0 + 2)] = f2tf32(v.z);
            kr[kperm(j0 + 3)] = f2tf32(v.w);
        }
#pragma unroll
        for (int c = 0; c < 4; c++) {
            const int d0 = vds + 4 * c;
            float4 v = *(const float4*)&Vp[vkey * HD + d0];
            Vt[(d0 + 0) * PVT + vpk] = f2tf32(v.x);
            Vt[(d0 + 1) * PVT + vpk] = f2tf32(v.y);
            Vt[(d0 + 2) * PVT + vpk] = f2tf32(v.z);
            Vt[(d0 + 3) * PVT + vpk] = f2tf32(v.w);
        }
        __syncthreads();

        if (jt == 2 * qt + 1 && wid < 4) continue;

        float s[8][4];
#pragma unroll
        for (int ni = 0; ni < 8; ni++)
#pragma unroll
            for (int r = 0; r < 4; r++) s[ni][r] = 0.f;
#pragma unroll
        for (int ks = 0; ks < 8; ks++) {
#pragma unroll
            for (int ni = 0; ni < 8; ni++) {
                uint64_t bv = *(const uint64_t*)&Ks[(ni * 8 + gr) * PKS + ks * 8 + 2 * tig];
                mma_tf32(s[ni], qa[ks][0], qa[ks][1], qa[ks][2], qa[ks][3],
                         (uint32_t)bv, (uint32_t)(bv >> 32));
            }
        }

        if (jt >= 2 * qt) {
            const int colb = jt * 64 + 2 * tig;
#pragma unroll
            for (int ni = 0; ni < 8; ni++) {
                const int c0 = colb + 8 * ni;
                if (c0 > row0) s[ni][0] = -INFINITY;
                if (c0 + 1 > row0) s[ni][1] = -INFINITY;
                if (c0 > row1) s[ni][2] = -INFINITY;
                if (c0 + 1 > row1) s[ni][3] = -INFINITY;
            }
        }

        float m0 = -INFINITY, m1 = -INFINITY;
#pragma unroll
        for (int ni = 0; ni < 8; ni++) {
            m0 = fmaxf(m0, fmaxf(s[ni][0], s[ni][1]));
            m1 = fmaxf(m1, fmaxf(s[ni][2], s[ni][3]));
        }
        m0 = fmaxf(m0, __shfl_xor_sync(0xffffffffu, m0, 1, 4));
        m0 = fmaxf(m0, __shfl_xor_sync(0xffffffffu, m0, 2, 4));
        m1 = fmaxf(m1, __shfl_xor_sync(0xffffffffu, m1, 1, 4));
        m1 = fmaxf(m1, __shfl_xor_sync(0xffffffffu, m1, 2, 4));
        const float mn0 = fmaxf(mrun0, m0);
        const float mn1 = fmaxf(mrun1, m1);
        const float al0 = __expf(mrun0 - mn0);
        const float al1 = __expf(mrun1 - mn1);
        float ls0 = 0.f, ls1 = 0.f;
        uint32_t pb[8][4];
#pragma unroll
        for (int ni = 0; ni < 8; ni++) {
            float p0 = __expf(s[ni][0] - mn0);
            float p1 = __expf(s[ni][1] - mn0);
            float p2 = __expf(s[ni][2] - mn1);
            float p3 = __expf(s[ni][3] - mn1);
            ls0 += p0 + p1;
            ls1 += p2 + p3;
            pb[ni][0] = f2tf32(p0);
            pb[ni][1] = f2tf32(p1);
            pb[ni][2] = f2tf32(p2);
            pb[ni][3] = f2tf32(p3);
            ctx[ni][0] *= al0;
            ctx[ni][1] *= al0;
            ctx[ni][2] *= al1;
            ctx[ni][3] *= al1;
        }
        ls0 += __shfl_xor_sync(0xffffffffu, ls0, 1, 4);
        ls0 += __shfl_xor_sync(0xffffffffu, ls0, 2, 4);
        ls1 += __shfl_xor_sync(0xffffffffu, ls1, 1, 4);
        ls1 += __shfl_xor_sync(0xffffffffu, ls1, 2, 4);
        mrun0 = mn0;
        mrun1 = mn1;
        lrun0 = lrun0 * al0 + ls0;
        lrun1 = lrun1 * al1 + ls1;

        const int sl0 = tig >> 1;
        const int sl1 = sl0 + 2;
        const bool odd = (tig & 1);
#pragma unroll
        for (int ks = 0; ks < 8; ks++) {
            uint32_t t0 = __shfl_sync(0xffffffffu, pb[ks][0], sl0, 4);
            uint32_t t1 = __shfl_sync(0xffffffffu, pb[ks][1], sl0, 4);
            uint32_t a0 = odd ? t1 : t0;
            t0 = __shfl_sync(0xffffffffu, pb[ks][0], sl1, 4);
            t1 = __shfl_sync(0xffffffffu, pb[ks][1], sl1, 4);
            uint32_t a2 = odd ? t1 : t0;
            t0 = __shfl_sync(0xffffffffu, pb[ks][2], sl0, 4);
            t1 = __shfl_sync(0xffffffffu, pb[ks][3], sl0, 4);
            uint32_t a1 = odd ? t1 : t0;
            t0 = __shfl_sync(0xffffffffu, pb[ks][2], sl1, 4);
            t1 = __shfl_sync(0xffffffffu, pb[ks][3], sl1, 4);
            uint32_t a3 = odd ? t1 : t0;
#pragma unroll
            for (int ni = 0; ni < 8; ni++) {
                uint64_t bv = *(const uint64_t*)&Vt[(ni * 8 + gr) * PVT + ks * 8 + 2 * tig];
                mma_tf32(ctx[ni], a0, a1, a2, a3, (uint32_t)bv, (uint32_t)(bv >> 32));
            }
        }
    }

    const float inv0 = 1.0f / lrun0;
    const float inv1 = 1.0f / lrun1;
    float* o0 = g_ctx + (((size_t)(b * T_SEQ + row0)) * NH + h) * HD;
    float* o1 = g_ctx + (((size_t)(b * T_SEQ + row1)) * NH + h) * HD;
#pragma unroll
    for (int ni = 0; ni < 8; ni++) {
        const int d = ni * 8 + 2 * tig;
        *(float2*)&o0[d] = make_float2(ctx[ni][0] * inv0, ctx[ni][1] * inv0);
        *(float2*)&o1[d] = make_float2(ctx[ni][2] * inv1, ctx[ni][3] * inv1);
    }
}

// ---------------------------------------------------------------------------
extern "C" void kernel_launch(void* const* d_in, const int* in_sizes, int n_in,
                              void* d_out, int out_size)
{
    const float* x    = (const float*)d_in[0];
    const float* cosT = (const float*)d_in[1];
    const float* sinT = (const float*)d_in[2];
    const float* wq   = (const float*)d_in[3];
    const float* bq   = (const float*)d_in[4];
    const float* wk   = (const float*)d_in[5];
    const float* bk   = (const float*)d_in[6];
    const float* wv   = (const float*)d_in[7];
    const float* bv   = (const float*)d_in[8];
    const float* wo   = (const float*)d_in[9];
    const float* bo   = (const float*)d_in[10];

    float* out  = (float*)d_out;            // (B, T, D)
    float* kout = out + (size_t)8388608;    // (B, KV, T, HD)
    float* vout = out + (size_t)10485760;   // (B, KV, T, HD)

    const int SMEM = 4 * TILE_W * 4;  // 81920 bytes
    static bool attr_set = false;
    if (!attr_set) {
        cudaFuncSetAttribute(db_gemm<0>, cudaFuncAttributeMaxDynamicSharedMemorySize, SMEM);
        cudaFuncSetAttribute(db_gemm<1>, cudaFuncAttributeMaxDynamicSharedMemorySize, SMEM);
        attr_set = true;
    }

    dim3 blk(256);

    // Fused Q/K/V projections (+RoPE for Q,K)
    db_gemm<0><<<dim3(24, 32), blk, SMEM>>>(
        x, wq, bq, wk, bk, wv, bv, kout, vout, nullptr, cosT, sinT);
    // Attention -> g_ctx
    attn_mma<<<dim3(T_SEQ / 128, 2 * NH), blk>>>(kout, vout);
    // Output projection -> out
    db_gemm<1><<<dim3(16, 32), blk, SMEM>>>(
        x, wo, bo, nullptr, nullptr, nullptr, nullptr, nullptr, nullptr, out,
        nullptr, nullptr);
}

// round 6
// speedup vs baseline: 1.2910x; 1.2910x over previous
#include <cuda_runtime.h>
#include <cstdint>
#include <math.h>

#define T_SEQ 2048
#define DMODEL 2048
#define NH 32
#define NKV 8
#define HD 64

// ---------------- Scratch (device globals; allocation-free) ----------------
__device__ float    g_q  [(size_t)2 * NH * T_SEQ * HD];   // fp32 (b,h,t,d)
__device__ uint32_t g_ctx[(size_t)2 * T_SEQ * NH * HD];   // tf32 (b,t,h,d)
__device__ uint32_t g_xt [(size_t)4096 * 2048];           // tf32 x
__device__ uint32_t g_wq [(size_t)2048 * 2048];
__device__ uint32_t g_wk [(size_t)512 * 2048];
__device__ uint32_t g_wv [(size_t)512 * 2048];
__device__ uint32_t g_wo [(size_t)2048 * 2048];
__device__ uint32_t g_kc [(size_t)2 * NKV * T_SEQ * HD];  // tf32 K (b,kv,t,d)
__device__ uint32_t g_vt [(size_t)2 * NKV * HD * T_SEQ];  // tf32 V^T (b,kv,d,t)

__device__ __forceinline__ uint32_t f2tf32(float f) {
    uint32_t u;
    asm("cvt.rna.tf32.f32 %0, %1;" : "=r"(u) : "f"(f));
    return u;
}

__device__ __forceinline__ void mma_tf32(float* c, uint32_t a0, uint32_t a1,
                                         uint32_t a2, uint32_t a3,
                                         uint32_t b0, uint32_t b1) {
    asm volatile(
        "mma.sync.aligned.m16n8k8.row.col.f32.tf32.tf32.f32 "
        "{%0,%1,%2,%3}, {%4,%5,%6,%7}, {%8,%9}, {%0,%1,%2,%3};"
        : "+f"(c[0]), "+f"(c[1]), "+f"(c[2]), "+f"(c[3])
        : "r"(a0), "r"(a1), "r"(a2), "r"(a3), "r"(b0), "r"(b1));
}

__device__ __forceinline__ uint32_t smem_u32(const void* p) {
    uint32_t a;
    asm("{ .reg .u64 t; cvta.to.shared.u64 t, %1; cvt.u32.u64 %0, t; }"
        : "=r"(a) : "l"(p));
    return a;
}
#define CP_ASYNC16(dst, src) \
    asm volatile("cp.async.ca.shared.global [%0], [%1], 16;" :: "r"(dst), "l"(src))
#define CP_COMMIT() asm volatile("cp.async.commit_group;" ::: "memory")
#define CP_WAIT0()  asm volatile("cp.async.wait_group 0;" ::: "memory")

// ============================================================================
// Prep: fp32 -> tf32 elementwise (vectorized)
// ============================================================================
__global__ void cvt_tf32(const float* __restrict__ in, uint32_t* __restrict__ out,
                         int n4)
{
    int i = blockIdx.x * blockDim.x + threadIdx.x;
    if (i >= n4) return;
    float4 v = ((const float4*)in)[i];
    uint4 o;
    o.x = f2tf32(v.x); o.y = f2tf32(v.y); o.z = f2tf32(v.z); o.w = f2tf32(v.w);
    ((uint4*)out)[i] = o;
}

// ============================================================================
// Prep: V (b,kv,t,d) fp32 -> V^T (b,kv,d,t) tf32 via smem tile transpose.
// grid = (T/64, 2*NKV), block = 256.
// ============================================================================
__global__ void vtrans(const float* __restrict__ vin, uint32_t* __restrict__ vt)
{
    __shared__ uint32_t ts[64 * 65];
    const int tid = threadIdx.x;
    const int jt = blockIdx.x;
    const int bkv = blockIdx.y;

    const float* in = vin + ((size_t)bkv * T_SEQ + jt * 64) * HD;
#pragma unroll
    for (int p = 0; p < 4; p++) {
        const int lin = p * 256 + tid;
        const int t = lin >> 4;
        const int dq = (lin & 15) * 4;
        float4 v = *(const float4*)&in[t * HD + dq];
        ts[(dq + 0) * 65 + t] = f2tf32(v.x);
        ts[(dq + 1) * 65 + t] = f2tf32(v.y);
        ts[(dq + 2) * 65 + t] = f2tf32(v.z);
        ts[(dq + 3) * 65 + t] = f2tf32(v.w);
    }
    __syncthreads();
    uint32_t* out = vt + (size_t)bkv * HD * T_SEQ + jt * 64;
#pragma unroll
    for (int p = 0; p < 4; p++) {
        const int lin = p * 256 + tid;
        const int d = lin >> 4;
        const int cq = (lin & 15) * 4;
        uint4 w;
        w.x = ts[d * 65 + cq + 0];
        w.y = ts[d * 65 + cq + 1];
        w.z = ts[d * 65 + cq + 2];
        w.w = ts[d * 65 + cq + 3];
        *(uint4*)&out[(size_t)d * T_SEQ + cq] = w;
    }
}

// ============================================================================
// cp.async double-buffered tf32 GEMM, 128x128 tile, BK=32, 8 warps (2x4).
// Operands are pre-converted tf32 (natural k order; slot relabeling makes the
// k pairing consistent between A and B fragments).
// KIND 0: fused QKV. bx<16: Q+RoPE->g_q ; 16..19: K+RoPE->kout ; 20..23: V->vout
// KIND 1: O projection: A=g_ctx(tf32), C=out fp32.
// ============================================================================
#define SPAD 40
#define TILE_W (128 * SPAD)

template <int KIND>
__global__ __launch_bounds__(256, 2) void db_gemm(
    const uint32_t* __restrict__ xA,
    const float* __restrict__ bq, const float* __restrict__ bk,
    const float* __restrict__ bv,
    float* __restrict__ kout, float* __restrict__ vout,
    float* __restrict__ outC,
    const float* __restrict__ cosT, const float* __restrict__ sinT)
{
    extern __shared__ __align__(16) uint32_t sm[];
    // layout: [buf0 A][buf0 B][buf1 A][buf1 B], each TILE_W words
    const uint32_t sm_addr = smem_u32(sm);

    const int tid = threadIdx.x;
    const int wid = tid >> 5;
    const int lane = tid & 31;
    const int gr = lane >> 2;
    const int tig = lane & 3;
    const int wm = wid >> 2;
    const int wn = wid & 3;

    constexpr int K = DMODEL;
    const int m0 = blockIdx.y * 128;

    int mode, n0;
    const uint32_t* A;
    const uint32_t* W;
    const float* bias;
    if (KIND == 1) {
        mode = 0; n0 = blockIdx.x * 128; A = g_ctx; W = g_wo; bias = bq;
    } else {
        const int bx = blockIdx.x;
        A = xA;
        if (bx < 16)      { mode = 1; n0 = bx * 128;        W = g_wq; bias = bq; }
        else if (bx < 20) { mode = 2; n0 = (bx - 16) * 128; W = g_wk; bias = bk; }
        else              { mode = 3; n0 = (bx - 20) * 128; W = g_wv; bias = bv; }
    }

    // cp.async assignment: 4 chunks A + 4 chunks B per thread per stage.
    const int rbase = tid >> 3;   // 0..31
    const int cg = tid & 7;       // 16B group
    const uint32_t* Asrc[4];
    const uint32_t* Wsrc[4];
    uint32_t dsto[4];
#pragma unroll
    for (int i = 0; i < 4; i++) {
        Asrc[i] = A + (size_t)(m0 + i * 32 + rbase) * K + cg * 4;
        Wsrc[i] = W + (size_t)(n0 + i * 32 + rbase) * K + cg * 4;
        dsto[i] = (uint32_t)(((i * 32 + rbase) * SPAD + cg * 4) * 4);
    }

    float acc[4][4][4];
#pragma unroll
    for (int mi = 0; mi < 4; mi++)
#pragma unroll
        for (int ni = 0; ni < 4; ni++)
#pragma unroll
            for (int r = 0; r < 4; r++) acc[mi][ni][r] = 0.f;

    const int NST = K / 32;
    // prologue: stage 0 -> buf 0
#pragma unroll
    for (int i = 0; i < 4; i++) {
        CP_ASYNC16(sm_addr + dsto[i], Asrc[i]);
        CP_ASYNC16(sm_addr + TILE_W * 4 + dsto[i], Wsrc[i]);
    }
    CP_COMMIT();

    for (int s = 0; s < NST; s++) {
        CP_WAIT0();
        __syncthreads();
        if (s + 1 < NST) {
            const uint32_t boff = (uint32_t)((s + 1) & 1) * (2 * TILE_W * 4);
            const int ko = (s + 1) * 32;
#pragma unroll
            for (int i = 0; i < 4; i++) {
                CP_ASYNC16(sm_addr + boff + dsto[i], Asrc[i] + ko);
                CP_ASYNC16(sm_addr + boff + TILE_W * 4 + dsto[i], Wsrc[i] + ko);
            }
            CP_COMMIT();
        }

        const uint32_t* Abase = sm + (s & 1) * 2 * TILE_W + (wm * 64) * SPAD;
        const uint32_t* Bbase = sm + (s & 1) * 2 * TILE_W + TILE_W + (wn * 32) * SPAD;
#pragma unroll
        for (int kk = 0; kk < 4; kk++) {
            const int kc = kk * 8 + 2 * tig;
            uint32_t bf[4][2];
#pragma unroll
            for (int ni = 0; ni < 4; ni++) {
                uint64_t bv = *(const uint64_t*)&Bbase[(ni * 8 + gr) * SPAD + kc];
                bf[ni][0] = (uint32_t)bv;
                bf[ni][1] = (uint32_t)(bv >> 32);
            }
#pragma unroll
            for (int mi = 0; mi < 4; mi++) {
                uint64_t a02 = *(const uint64_t*)&Abase[(mi * 16 + gr) * SPAD + kc];
                uint64_t a13 = *(const uint64_t*)&Abase[(mi * 16 + gr + 8) * SPAD + kc];
                uint32_t a0 = (uint32_t)a02, a2 = (uint32_t)(a02 >> 32);
                uint32_t a1 = (uint32_t)a13, a3 = (uint32_t)(a13 >> 32);
#pragma unroll
                for (int ni = 0; ni < 4; ni++)
                    mma_tf32(acc[mi][ni], a0, a1, a2, a3, bf[ni][0], bf[ni][1]);
            }
        }
    }

    // ---------------- Register epilogue ----------------
#pragma unroll
    for (int mi = 0; mi < 4; mi++) {
#pragma unroll
        for (int half = 0; half < 2; half++) {
            const int m = m0 + wm * 64 + mi * 16 + gr + half * 8;
            const int bb = m >> 11;
            const int t = m & (T_SEQ - 1);
#pragma unroll
            for (int ni = 0; ni < 4; ni++) {
                const int n = n0 + wn * 32 + ni * 8 + tig * 2;
                float v0 = acc[mi][ni][half * 2 + 0] + bias[n];
                float v1 = acc[mi][ni][half * 2 + 1] + bias[n + 1];
                if (mode == 1 || mode == 2) {
                    const int hh = (n & 63) >> 1;
                    const float c = cosT[t * (HD / 2) + hh];
                    const float ss = sinT[t * (HD / 2) + hh];
                    const float e = v0 * c - v1 * ss;
                    const float o = v0 * ss + v1 * c;
                    v0 = e;
                    v1 = o;
                }
                if (mode == 0) {
                    *(float2*)&outC[(size_t)m * DMODEL + n] = make_float2(v0, v1);
                } else if (mode == 1) {
                    *(float2*)&g_q[(((size_t)(bb * NH + (n >> 6))) * T_SEQ + t) * HD + (n & 63)] =
                        make_float2(v0, v1);
                } else {
                    float* dst = (mode == 2) ? kout : vout;
                    *(float2*)&dst[(((size_t)(bb * NKV + (n >> 6))) * T_SEQ + t) * HD + (n & 63)] =
                        make_float2(v0, v1);
                }
            }
        }
    }
}

// ============================================================================
// Flash attention, tf32 mma.sync, cp.async double-buffered K/V tiles.
// Q tile 128 (grid.x=16), key tile 64, 8 warps (16 rows each).
// Natural layouts + slot relabeling: NO shuffles for P->A, no permutes.
// Pitch 72 (== 8 mod 32): conflict-free LDS.64 fragment reads.
// ============================================================================
#define ATP 72
#define KTILE_W (64 * ATP)   // 4608 words

__global__ __launch_bounds__(256, 2) void attn_mma()
{
    extern __shared__ __align__(16) uint32_t sm[];
    // [Ks buf0][Ks buf1][Vt buf0][Vt buf1] each KTILE_W
    const uint32_t sm_addr = smem_u32(sm);

    const int tid = threadIdx.x;
    const int wid = tid >> 5;
    const int lane = tid & 31;
    const int gr = lane >> 2;
    const int tig = lane & 3;

    const int qt = blockIdx.x;
    const int bh = blockIdx.y;
    const int b = bh >> 5;
    const int h = bh & 31;
    const int bkv = (b * NKV) + (h >> 2);

    // Q fragments, relabeled: slot pair = physical d (8ks+2tig, 8ks+2tig+1)
    const float* Qg = g_q + (((size_t)(b * NH + h)) * T_SEQ + qt * 128 + wid * 16) * HD;
    uint32_t qa[8][4];
#pragma unroll
    for (int ks = 0; ks < 8; ks++) {
        const int d0 = 8 * ks + 2 * tig;
        qa[ks][0] = f2tf32(Qg[gr * HD + d0] * 0.125f);
        qa[ks][1] = f2tf32(Qg[(gr + 8) * HD + d0] * 0.125f);
        qa[ks][2] = f2tf32(Qg[gr * HD + d0 + 1] * 0.125f);
        qa[ks][3] = f2tf32(Qg[(gr + 8) * HD + d0 + 1] * 0.125f);
    }

    const uint32_t* Kbase = g_kc + (size_t)bkv * T_SEQ * HD;
    const uint32_t* Vbase = g_vt + (size_t)bkv * HD * T_SEQ;

    float ctx[8][4];
#pragma unroll
    for (int ni = 0; ni < 8; ni++)
#pragma unroll
        for (int r = 0; r < 4; r++) ctx[ni][r] = 0.f;
    float mrun0 = -INFINITY, mrun1 = -INFINITY;
    float lrun0 = 0.f, lrun1 = 0.f;

    // loader: 4 chunks K + 4 chunks V per thread
    const int lrow = tid >> 2;          // 0..63 (key for K, d for V)
    const int lcol = (tid & 3) * 16;    // word offset within 64, per 4 chunks
    const int row0 = qt * 128 + wid * 16 + gr;
    const int row1 = row0 + 8;
    const int njt = 2 * qt + 2;

    // prologue: tile 0 -> buf 0
#pragma unroll
    for (int c = 0; c < 4; c++) {
        const int col = lcol + 4 * c;
        CP_ASYNC16(sm_addr + (lrow * ATP + col) * 4, Kbase + (size_t)lrow * HD + col);
        CP_ASYNC16(sm_addr + (2 * KTILE_W + lrow * ATP + col) * 4,
                   Vbase + (size_t)lrow * T_SEQ + col);
    }
    CP_COMMIT();

    for (int jt = 0; jt < njt; jt++) {
        CP_WAIT0();
        __syncthreads();
        if (jt + 1 < njt) {
            const uint32_t boff = (uint32_t)((jt + 1) & 1) * KTILE_W * 4;
            const int kt = (jt + 1) * 64;
#pragma unroll
            for (int c = 0; c < 4; c++) {
                const int col = lcol + 4 * c;
                CP_ASYNC16(sm_addr + boff + (lrow * ATP + col) * 4,
                           Kbase + (size_t)(kt + lrow) * HD + col);
                CP_ASYNC16(sm_addr + 2 * KTILE_W * 4 + boff + (lrow * ATP + col) * 4,
                           Vbase + (size_t)lrow * T_SEQ + kt + col);
            }
            CP_COMMIT();
        }

        if (jt == 2 * qt + 1 && wid < 4) continue;  // fully masked

        const uint32_t* Ks = sm + (jt & 1) * KTILE_W;
        const uint32_t* Vt = sm + 2 * KTILE_W + (jt & 1) * KTILE_W;

        // ---- S = Q K^T ----
        float s[8][4];
#pragma unroll
        for (int ni = 0; ni < 8; ni++)
#pragma unroll
            for (int r = 0; r < 4; r++) s[ni][r] = 0.f;
#pragma unroll
        for (int ks = 0; ks < 8; ks++) {
#pragma unroll
            for (int ni = 0; ni < 8; ni++) {
                uint64_t bv = *(const uint64_t*)&Ks[(ni * 8 + gr) * ATP + ks * 8 + 2 * tig];
                mma_tf32(s[ni], qa[ks][0], qa[ks][1], qa[ks][2], qa[ks][3],
                         (uint32_t)bv, (uint32_t)(bv >> 32));
            }
        }

        // ---- causal mask ----
        if (jt >= 2 * qt) {
            const int colb = jt * 64 + 2 * tig;
#pragma unroll
            for (int ni = 0; ni < 8; ni++) {
                const int c0 = colb + 8 * ni;
                if (c0 > row0) s[ni][0] = -INFINITY;
                if (c0 + 1 > row0) s[ni][1] = -INFINITY;
                if (c0 > row1) s[ni][2] = -INFINITY;
                if (c0 + 1 > row1) s[ni][3] = -INFINITY;
            }
        }

        // ---- online softmax ----
        float m0 = -INFINITY, m1 = -INFINITY;
#pragma unroll
        for (int ni = 0; ni < 8; ni++) {
            m0 = fmaxf(m0, fmaxf(s[ni][0], s[ni][1]));
            m1 = fmaxf(m1, fmaxf(s[ni][2], s[ni][3]));
        }
        m0 = fmaxf(m0, __shfl_xor_sync(0xffffffffu, m0, 1, 4));
        m0 = fmaxf(m0, __shfl_xor_sync(0xffffffffu, m0, 2, 4));
        m1 = fmaxf(m1, __shfl_xor_sync(0xffffffffu, m1, 1, 4));
        m1 = fmaxf(m1, __shfl_xor_sync(0xffffffffu, m1, 2, 4));
        const float mn0 = fmaxf(mrun0, m0);
        const float mn1 = fmaxf(mrun1, m1);
        const float al0 = __expf(mrun0 - mn0);
        const float al1 = __expf(mrun1 - mn1);
        float ls0 = 0.f, ls1 = 0.f;
        uint32_t pb[8][4];
#pragma unroll
        for (int ni = 0; ni < 8; ni++) {
            float p0 = __expf(s[ni][0] - mn0);
            float p1 = __expf(s[ni][1] - mn0);
            float p2 = __expf(s[ni][2] - mn1);
            float p3 = __expf(s[ni][3] - mn1);
            ls0 += p0 + p1;
            ls1 += p2 + p3;
            pb[ni][0] = f2tf32(p0);
            pb[ni][1] = f2tf32(p1);
            pb[ni][2] = f2tf32(p2);
            pb[ni][3] = f2tf32(p3);
            ctx[ni][0] *= al0;
            ctx[ni][1] *= al0;
            ctx[ni][2] *= al1;
            ctx[ni][3] *= al1;
        }
        ls0 += __shfl_xor_sync(0xffffffffu, ls0, 1, 4);
        ls0 += __shfl_xor_sync(0xffffffffu, ls0, 2, 4);
        ls1 += __shfl_xor_sync(0xffffffffu, ls1, 1, 4);
        ls1 += __shfl_xor_sync(0xffffffffu, ls1, 2, 4);
        mrun0 = mn0;
        mrun1 = mn1;
        lrun0 = lrun0 * al0 + ls0;
        lrun1 = lrun1 * al1 + ls1;

        // ---- ctx += P V : P C-fragment IS the A-fragment under relabeling ----
#pragma unroll
        for (int ks = 0; ks < 8; ks++) {
#pragma unroll
            for (int ni = 0; ni < 8; ni++) {
                uint64_t bv = *(const uint64_t*)&Vt[(ni * 8 + gr) * ATP + ks * 8 + 2 * tig];
                mma_tf32(ctx[ni], pb[ks][0], pb[ks][2], pb[ks][1], pb[ks][3],
                         (uint32_t)bv, (uint32_t)(bv >> 32));
            }
        }
    }

    // ---- finalize: write g_ctx as tf32 (natural d order) ----
    const float inv0 = 1.0f / lrun0;
    const float inv1 = 1.0f / lrun1;
    uint32_t* o0 = g_ctx + (((size_t)(b * T_SEQ + row0)) * NH + h) * HD;
    uint32_t* o1 = g_ctx + (((size_t)(b * T_SEQ + row1)) * NH + h) * HD;
#pragma unroll
    for (int ni = 0; ni < 8; ni++) {
        const int d = ni * 8 + 2 * tig;
        uint2 w0, w1;
        w0.x = f2tf32(ctx[ni][0] * inv0);
        w0.y = f2tf32(ctx[ni][1] * inv0);
        w1.x = f2tf32(ctx[ni][2] * inv1);
        w1.y = f2tf32(ctx[ni][3] * inv1);
        *(uint2*)&o0[d] = w0;
        *(uint2*)&o1[d] = w1;
    }
}

// ---------------------------------------------------------------------------
extern "C" void kernel_launch(void* const* d_in, const int* in_sizes, int n_in,
                              void* d_out, int out_size)
{
    const float* x    = (const float*)d_in[0];
    const float* cosT = (const float*)d_in[1];
    const float* sinT = (const float*)d_in[2];
    const float* wq   = (const float*)d_in[3];
    const float* bq   = (const float*)d_in[4];
    const float* wk   = (const float*)d_in[5];
    const float* bk   = (const float*)d_in[6];
    const float* wv   = (const float*)d_in[7];
    const float* bv   = (const float*)d_in[8];
    const float* wo   = (const float*)d_in[9];
    const float* bo   = (const float*)d_in[10];

    float* out  = (float*)d_out;            // (B, T, D)
    float* kout = out + (size_t)8388608;    // (B, KV, T, HD)
    float* vout = out + (size_t)10485760;   // (B, KV, T, HD)

    const int GEMM_SMEM = 4 * TILE_W * 4;    // 81920 B
    const int ATTN_SMEM = 4 * KTILE_W * 4;   // 73728 B
    static bool attr_set = false;
    if (!attr_set) {
        cudaFuncSetAttribute(db_gemm<0>, cudaFuncAttributeMaxDynamicSharedMemorySize, GEMM_SMEM);
        cudaFuncSetAttribute(db_gemm<1>, cudaFuncAttributeMaxDynamicSharedMemorySize, GEMM_SMEM);
        cudaFuncSetAttribute(attn_mma, cudaFuncAttributeMaxDynamicSharedMemorySize, ATTN_SMEM);
        attr_set = true;
    }

    uint32_t* p_xt;  cudaGetSymbolAddress((void**)&p_xt, g_xt);
    uint32_t* p_wq;  cudaGetSymbolAddress((void**)&p_wq, g_wq);
    uint32_t* p_wk;  cudaGetSymbolAddress((void**)&p_wk, g_wk);
    uint32_t* p_wv;  cudaGetSymbolAddress((void**)&p_wv, g_wv);
    uint32_t* p_wo;  cudaGetSymbolAddress((void**)&p_wo, g_wo);
    uint32_t* p_kc;  cudaGetSymbolAddress((void**)&p_kc, g_kc);
    uint32_t* p_vt;  cudaGetSymbolAddress((void**)&p_vt, g_vt);

    dim3 blk(256);

    // Prep: fp32 -> tf32
    cvt_tf32<<<8192, 256>>>(x, p_xt, 2097152);
    cvt_tf32<<<4096, 256>>>(wq, p_wq, 1048576);
    cvt_tf32<<<1024, 256>>>(wk, p_wk, 262144);
    cvt_tf32<<<1024, 256>>>(wv, p_wv, 262144);
    cvt_tf32<<<4096, 256>>>(wo, p_wo, 1048576);

    // Fused QKV projections (+RoPE for Q,K)
    db_gemm<0><<<dim3(24, 32), blk, GEMM_SMEM>>>(
        p_xt, bq, bk, bv, kout, vout, nullptr, cosT, sinT);

    // K -> tf32 copy; V -> transposed tf32
    cvt_tf32<<<2048, 256>>>(kout, p_kc, 524288);
    vtrans<<<dim3(32, 16), blk>>>(vout, p_vt);

    // Attention -> g_ctx (tf32)
    attn_mma<<<dim3(T_SEQ / 128, 2 * NH), blk, ATTN_SMEM>>>();

    // Output projection -> out
    db_gemm<1><<<dim3(16, 32), blk, GEMM_SMEM>>>(
        nullptr, bo, nullptr, nullptr, nullptr, nullptr, out, nullptr, nullptr);
}

// round 7
// speedup vs baseline: 1.3152x; 1.0187x over previous
#include <cuda_runtime.h>
#include <cstdint>
#include <math.h>

#define T_SEQ 2048
#define DMODEL 2048
#define NH 32
#define NKV 8
#define HD 64

// ---------------- Scratch (device globals; allocation-free) ----------------
__device__ float    g_q  [(size_t)2 * NH * T_SEQ * HD];   // fp32 (b,h,t,d)
__device__ uint32_t g_ctx[(size_t)2 * T_SEQ * NH * HD];   // tf32 (b,t,h,d)
__device__ uint32_t g_xt [(size_t)4096 * 2048];           // tf32 x
__device__ uint32_t g_wq [(size_t)2048 * 2048];
__device__ uint32_t g_wk [(size_t)512 * 2048];
__device__ uint32_t g_wv [(size_t)512 * 2048];
__device__ uint32_t g_wo [(size_t)2048 * 2048];
__device__ uint32_t g_kc [(size_t)2 * NKV * T_SEQ * HD];  // tf32 K (b,kv,t,d)
__device__ uint32_t g_vt [(size_t)2 * NKV * HD * T_SEQ];  // tf32 V^T (b,kv,d,t)

__device__ __forceinline__ uint32_t f2tf32(float f) {
    uint32_t u;
    asm("cvt.rna.tf32.f32 %0, %1;" : "=r"(u) : "f"(f));
    return u;
}

__device__ __forceinline__ void mma_tf32(float* c, uint32_t a0, uint32_t a1,
                                         uint32_t a2, uint32_t a3,
                                         uint32_t b0, uint32_t b1) {
    asm volatile(
        "mma.sync.aligned.m16n8k8.row.col.f32.tf32.tf32.f32 "
        "{%0,%1,%2,%3}, {%4,%5,%6,%7}, {%8,%9}, {%0,%1,%2,%3};"
        : "+f"(c[0]), "+f"(c[1]), "+f"(c[2]), "+f"(c[3])
        : "r"(a0), "r"(a1), "r"(a2), "r"(a3), "r"(b0), "r"(b1));
}

__device__ __forceinline__ uint32_t smem_u32(const void* p) {
    uint32_t a;
    asm("{ .reg .u64 t; cvta.to.shared.u64 t, %1; cvt.u32.u64 %0, t; }"
        : "=r"(a) : "l"(p));
    return a;
}
#define CP_ASYNC16(dst, src) \
    asm volatile("cp.async.ca.shared.global [%0], [%1], 16;" :: "r"(dst), "l"(src))
#define CP_COMMIT() asm volatile("cp.async.commit_group;" ::: "memory")
#define CP_WAIT0()  asm volatile("cp.async.wait_group 0;" ::: "memory")

// ============================================================================
// Prep: all fp32 -> tf32 conversions in ONE kernel (5 regions).
// Region sizes in float4 units: x 2097152 | wq 1048576 | wk 262144 |
// wv 262144 | wo 1048576. Total 4718592 float4 -> grid 18432 x 256.
// ============================================================================
__global__ void cvt_all(const float* __restrict__ x,
                        const float* __restrict__ wq,
                        const float* __restrict__ wk,
                        const float* __restrict__ wv,
                        const float* __restrict__ wo,
                        uint32_t* __restrict__ xt,
                        uint32_t* __restrict__ wqt,
                        uint32_t* __restrict__ wkt,
                        uint32_t* __restrict__ wvt,
                        uint32_t* __restrict__ wot)
{
    int i = blockIdx.x * blockDim.x + threadIdx.x;
    const float* in;
    uint32_t* out;
    if (i < 2097152)        { in = x;  out = xt; }
    else if (i < 3145728)   { in = wq; out = wqt; i -= 2097152; }
    else if (i < 3407872)   { in = wk; out = wkt; i -= 3145728; }
    else if (i < 3670016)   { in = wv; out = wvt; i -= 3407872; }
    else                    { in = wo; out = wot; i -= 3670016; }
    float4 v = ((const float4*)in)[i];
    uint4 o;
    o.x = f2tf32(v.x); o.y = f2tf32(v.y); o.z = f2tf32(v.z); o.w = f2tf32(v.w);
    ((uint4*)out)[i] = o;
}

// ============================================================================
// Prep: V (b,kv,t,d) fp32 -> V^T (b,kv,d,t) tf32 via smem tile transpose.
// ============================================================================
__global__ void vtrans(const float* __restrict__ vin, uint32_t* __restrict__ vt)
{
    __shared__ uint32_t ts[64 * 65];
    const int tid = threadIdx.x;
    const int jt = blockIdx.x;
    const int bkv = blockIdx.y;

    const float* in = vin + ((size_t)bkv * T_SEQ + jt * 64) * HD;
#pragma unroll
    for (int p = 0; p < 4; p++) {
        const int lin = p * 256 + tid;
        const int t = lin >> 4;
        const int dq = (lin & 15) * 4;
        float4 v = *(const float4*)&in[t * HD + dq];
        ts[(dq + 0) * 65 + t] = f2tf32(v.x);
        ts[(dq + 1) * 65 + t] = f2tf32(v.y);
        ts[(dq + 2) * 65 + t] = f2tf32(v.z);
        ts[(dq + 3) * 65 + t] = f2tf32(v.w);
    }
    __syncthreads();
    uint32_t* out = vt + (size_t)bkv * HD * T_SEQ + jt * 64;
#pragma unroll
    for (int p = 0; p < 4; p++) {
        const int lin = p * 256 + tid;
        const int d = lin >> 4;
        const int cq = (lin & 15) * 4;
        uint4 w;
        w.x = ts[d * 65 + cq + 0];
        w.y = ts[d * 65 + cq + 1];
        w.z = ts[d * 65 + cq + 2];
        w.w = ts[d * 65 + cq + 3];
        *(uint4*)&out[(size_t)d * T_SEQ + cq] = w;
    }
}

// ============================================================================
// cp.async double-buffered tf32 GEMM (as R6, + fused K tf32 write in mode 2).
// ============================================================================
#define SPAD 40
#define TILE_W (128 * SPAD)

template <int KIND>
__global__ __launch_bounds__(256, 2) void db_gemm(
    const uint32_t* __restrict__ xA,
    const float* __restrict__ bq, const float* __restrict__ bk,
    const float* __restrict__ bv,
    float* __restrict__ kout, float* __restrict__ vout,
    float* __restrict__ outC,
    const float* __restrict__ cosT, const float* __restrict__ sinT)
{
    extern __shared__ __align__(16) uint32_t sm[];
    const uint32_t sm_addr = smem_u32(sm);

    const int tid = threadIdx.x;
    const int wid = tid >> 5;
    const int lane = tid & 31;
    const int gr = lane >> 2;
    const int tig = lane & 3;
    const int wm = wid >> 2;
    const int wn = wid & 3;

    constexpr int K = DMODEL;
    const int m0 = blockIdx.y * 128;

    int mode, n0;
    const uint32_t* A;
    const uint32_t* W;
    const float* bias;
    if (KIND == 1) {
        mode = 0; n0 = blockIdx.x * 128; A = g_ctx; W = g_wo; bias = bq;
    } else {
        const int bx = blockIdx.x;
        A = xA;
        if (bx < 16)      { mode = 1; n0 = bx * 128;        W = g_wq; bias = bq; }
        else if (bx < 20) { mode = 2; n0 = (bx - 16) * 128; W = g_wk; bias = bk; }
        else              { mode = 3; n0 = (bx - 20) * 128; W = g_wv; bias = bv; }
    }

    const int rbase = tid >> 3;
    const int cg = tid & 7;
    const uint32_t* Asrc[4];
    const uint32_t* Wsrc[4];
    uint32_t dsto[4];
#pragma unroll
    for (int i = 0; i < 4; i++) {
        Asrc[i] = A + (size_t)(m0 + i * 32 + rbase) * K + cg * 4;
        Wsrc[i] = W + (size_t)(n0 + i * 32 + rbase) * K + cg * 4;
        dsto[i] = (uint32_t)(((i * 32 + rbase) * SPAD + cg * 4) * 4);
    }

    float acc[4][4][4];
#pragma unroll
    for (int mi = 0; mi < 4; mi++)
#pragma unroll
        for (int ni = 0; ni < 4; ni++)
#pragma unroll
            for (int r = 0; r < 4; r++) acc[mi][ni][r] = 0.f;

    const int NST = K / 32;
#pragma unroll
    for (int i = 0; i < 4; i++) {
        CP_ASYNC16(sm_addr + dsto[i], Asrc[i]);
        CP_ASYNC16(sm_addr + TILE_W * 4 + dsto[i], Wsrc[i]);
    }
    CP_COMMIT();

    for (int s = 0; s < NST; s++) {
        CP_WAIT0();
        __syncthreads();
        if (s + 1 < NST) {
            const uint32_t boff = (uint32_t)((s + 1) & 1) * (2 * TILE_W * 4);
            const int ko = (s + 1) * 32;
#pragma unroll
            for (int i = 0; i < 4; i++) {
                CP_ASYNC16(sm_addr + boff + dsto[i], Asrc[i] + ko);
                CP_ASYNC16(sm_addr + boff + TILE_W * 4 + dsto[i], Wsrc[i] + ko);
            }
            CP_COMMIT();
        }

        const uint32_t* Abase = sm + (s & 1) * 2 * TILE_W + (wm * 64) * SPAD;
        const uint32_t* Bbase = sm + (s & 1) * 2 * TILE_W + TILE_W + (wn * 32) * SPAD;
#pragma unroll
        for (int kk = 0; kk < 4; kk++) {
            const int kc = kk * 8 + 2 * tig;
            uint32_t bf[4][2];
#pragma unroll
            for (int ni = 0; ni < 4; ni++) {
                uint64_t bv = *(const uint64_t*)&Bbase[(ni * 8 + gr) * SPAD + kc];
                bf[ni][0] = (uint32_t)bv;
                bf[ni][1] = (uint32_t)(bv >> 32);
            }
#pragma unroll
            for (int mi = 0; mi < 4; mi++) {
                uint64_t a02 = *(const uint64_t*)&Abase[(mi * 16 + gr) * SPAD + kc];
                uint64_t a13 = *(const uint64_t*)&Abase[(mi * 16 + gr + 8) * SPAD + kc];
                uint32_t a0 = (uint32_t)a02, a2 = (uint32_t)(a02 >> 32);
                uint32_t a1 = (uint32_t)a13, a3 = (uint32_t)(a13 >> 32);
#pragma unroll
                for (int ni = 0; ni < 4; ni++)
                    mma_tf32(acc[mi][ni], a0, a1, a2, a3, bf[ni][0], bf[ni][1]);
            }
        }
    }

    // ---------------- Register epilogue ----------------
#pragma unroll
    for (int mi = 0; mi < 4; mi++) {
#pragma unroll
        for (int half = 0; half < 2; half++) {
            const int m = m0 + wm * 64 + mi * 16 + gr + half * 8;
            const int bb = m >> 11;
            const int t = m & (T_SEQ - 1);
#pragma unroll
            for (int ni = 0; ni < 4; ni++) {
                const int n = n0 + wn * 32 + ni * 8 + tig * 2;
                float v0 = acc[mi][ni][half * 2 + 0] + bias[n];
                float v1 = acc[mi][ni][half * 2 + 1] + bias[n + 1];
                if (mode == 1 || mode == 2) {
                    const int hh = (n & 63) >> 1;
                    const float c = cosT[t * (HD / 2) + hh];
                    const float ss = sinT[t * (HD / 2) + hh];
                    const float e = v0 * c - v1 * ss;
                    const float o = v0 * ss + v1 * c;
                    v0 = e;
                    v1 = o;
                }
                if (mode == 0) {
                    *(float2*)&outC[(size_t)m * DMODEL + n] = make_float2(v0, v1);
                } else if (mode == 1) {
                    *(float2*)&g_q[(((size_t)(bb * NH + (n >> 6))) * T_SEQ + t) * HD + (n & 63)] =
                        make_float2(v0, v1);
                } else {
                    const size_t idx =
                        (((size_t)(bb * NKV + (n >> 6))) * T_SEQ + t) * HD + (n & 63);
                    if (mode == 2) {
                        *(float2*)&kout[idx] = make_float2(v0, v1);
                        // fused tf32 K for the attention kernel
                        uint2 kq;
                        kq.x = f2tf32(v0);
                        kq.y = f2tf32(v1);
                        *(uint2*)&g_kc[idx] = kq;
                    } else {
                        *(float2*)&vout[idx] = make_float2(v0, v1);
                    }
                }
            }
        }
    }
}

// ============================================================================
// Flash attention (as R6) + heavy-first q-tile scheduling.
// ============================================================================
#define ATP 72
#define KTILE_W (64 * ATP)

__global__ __launch_bounds__(256, 2) void attn_mma()
{
    extern __shared__ __align__(16) uint32_t sm[];
    const uint32_t sm_addr = smem_u32(sm);

    const int tid = threadIdx.x;
    const int wid = tid >> 5;
    const int lane = tid & 31;
    const int gr = lane >> 2;
    const int tig = lane & 3;

    const int qt = (gridDim.x - 1) - blockIdx.x;  // heavy-first schedule
    const int bh = blockIdx.y;
    const int b = bh >> 5;
    const int h = bh & 31;
    const int bkv = (b * NKV) + (h >> 2);

    const float* Qg = g_q + (((size_t)(b * NH + h)) * T_SEQ + qt * 128 + wid * 16) * HD;
    uint32_t qa[8][4];
#pragma unroll
    for (int ks = 0; ks < 8; ks++) {
        const int d0 = 8 * ks + 2 * tig;
        qa[ks][0] = f2tf32(Qg[gr * HD + d0] * 0.125f);
        qa[ks][1] = f2tf32(Qg[(gr + 8) * HD + d0] * 0.125f);
        qa[ks][2] = f2tf32(Qg[gr * HD + d0 + 1] * 0.125f);
        qa[ks][3] = f2tf32(Qg[(gr + 8) * HD + d0 + 1] * 0.125f);
    }

    const uint32_t* Kbase = g_kc + (size_t)bkv * T_SEQ * HD;
    const uint32_t* Vbase = g_vt + (size_t)bkv * HD * T_SEQ;

    float ctx[8][4];
#pragma unroll
    for (int ni = 0; ni < 8; ni++)
#pragma unroll
        for (int r = 0; r < 4; r++) ctx[ni][r] = 0.f;
    float mrun0 = -INFINITY, mrun1 = -INFINITY;
    float lrun0 = 0.f, lrun1 = 0.f;

    const int lrow = tid >> 2;
    const int lcol = (tid & 3) * 16;
    const int row0 = qt * 128 + wid * 16 + gr;
    const int row1 = row0 + 8;
    const int njt = 2 * qt + 2;

#pragma unroll
    for (int c = 0; c < 4; c++) {
        const int col = lcol + 4 * c;
        CP_ASYNC16(sm_addr + (lrow * ATP + col) * 4, Kbase + (size_t)lrow * HD + col);
        CP_ASYNC16(sm_addr + (2 * KTILE_W + lrow * ATP + col) * 4,
                   Vbase + (size_t)lrow * T_SEQ + col);
    }
    CP_COMMIT();

    for (int jt = 0; jt < njt; jt++) {
        CP_WAIT0();
        __syncthreads();
        if (jt + 1 < njt) {
            const uint32_t boff = (uint32_t)((jt + 1) & 1) * KTILE_W * 4;
            const int kt = (jt + 1) * 64;
#pragma unroll
            for (int c = 0; c < 4; c++) {
                const int col = lcol + 4 * c;
                CP_ASYNC16(sm_addr + boff + (lrow * ATP + col) * 4,
                           Kbase + (size_t)(kt + lrow) * HD + col);
                CP_ASYNC16(sm_addr + 2 * KTILE_W * 4 + boff + (lrow * ATP + col) * 4,
                           Vbase + (size_t)lrow * T_SEQ + kt + col);
            }
            CP_COMMIT();
        }

        if (jt == 2 * qt + 1 && wid < 4) continue;

        const uint32_t* Ks = sm + (jt & 1) * KTILE_W;
        const uint32_t* Vt = sm + 2 * KTILE_W + (jt & 1) * KTILE_W;

        float s[8][4];
#pragma unroll
        for (int ni = 0; ni < 8; ni++)
#pragma unroll
            for (int r = 0; r < 4; r++) s[ni][r] = 0.f;
#pragma unroll
        for (int ks = 0; ks < 8; ks++) {
#pragma unroll
            for (int ni = 0; ni < 8; ni++) {
                uint64_t bv = *(const uint64_t*)&Ks[(ni * 8 + gr) * ATP + ks * 8 + 2 * tig];
                mma_tf32(s[ni], qa[ks][0], qa[ks][1], qa[ks][2], qa[ks][3],
                         (uint32_t)bv, (uint32_t)(bv >> 32));
            }
        }

        if (jt >= 2 * qt) {
            const int colb = jt * 64 + 2 * tig;
#pragma unroll
            for (int ni = 0; ni < 8; ni++) {
                const int c0 = colb + 8 * ni;
                if (c0 > row0) s[ni][0] = -INFINITY;
                if (c0 + 1 > row0) s[ni][1] = -INFINITY;
                if (c0 > row1) s[ni][2] = -INFINITY;
                if (c0 + 1 > row1) s[ni][3] = -INFINITY;
            }
        }

        float m0 = -INFINITY, m1 = -INFINITY;
#pragma unroll
        for (int ni = 0; ni < 8; ni++) {
            m0 = fmaxf(m0, fmaxf(s[ni][0], s[ni][1]));
            m1 = fmaxf(m1, fmaxf(s[ni][2], s[ni][3]));
        }
        m0 = fmaxf(m0, __shfl_xor_sync(0xffffffffu, m0, 1, 4));
        m0 = fmaxf(m0, __shfl_xor_sync(0xffffffffu, m0, 2, 4));
        m1 = fmaxf(m1, __shfl_xor_sync(0xffffffffu, m1, 1, 4));
        m1 = fmaxf(m1, __shfl_xor_sync(0xffffffffu, m1, 2, 4));
        const float mn0 = fmaxf(mrun0, m0);
        const float mn1 = fmaxf(mrun1, m1);
        const float al0 = __expf(mrun0 - mn0);
        const float al1 = __expf(mrun1 - mn1);
        float ls0 = 0.f, ls1 = 0.f;
        uint32_t pb[8][4];
#pragma unroll
        for (int ni = 0; ni < 8; ni++) {
            float p0 = __expf(s[ni][0] - mn0);
            float p1 = __expf(s[ni][1] - mn0);
            float p2 = __expf(s[ni][2] - mn1);
            float p3 = __expf(s[ni][3] - mn1);
            ls0 += p0 + p1;
            ls1 += p2 + p3;
            pb[ni][0] = f2tf32(p0);
            pb[ni][1] = f2tf32(p1);
            pb[ni][2] = f2tf32(p2);
            pb[ni][3] = f2tf32(p3);
            ctx[ni][0] *= al0;
            ctx[ni][1] *= al0;
            ctx[ni][2] *= al1;
            ctx[ni][3] *= al1;
        }
        ls0 += __shfl_xor_sync(0xffffffffu, ls0, 1, 4);
        ls0 += __shfl_xor_sync(0xffffffffu, ls0, 2, 4);
        ls1 += __shfl_xor_sync(0xffffffffu, ls1, 1, 4);
        ls1 += __shfl_xor_sync(0xffffffffu, ls1, 2, 4);
        mrun0 = mn0;
        mrun1 = mn1;
        lrun0 = lrun0 * al0 + ls0;
        lrun1 = lrun1 * al1 + ls1;

#pragma unroll
        for (int ks = 0; ks < 8; ks++) {
#pragma unroll
            for (int ni = 0; ni < 8; ni++) {
                uint64_t bv = *(const uint64_t*)&Vt[(ni * 8 + gr) * ATP + ks * 8 + 2 * tig];
                mma_tf32(ctx[ni], pb[ks][0], pb[ks][2], pb[ks][1], pb[ks][3],
                         (uint32_t)bv, (uint32_t)(bv >> 32));
            }
        }
    }

    const float inv0 = 1.0f / lrun0;
    const float inv1 = 1.0f / lrun1;
    uint32_t* o0 = g_ctx + (((size_t)(b * T_SEQ + row0)) * NH + h) * HD;
    uint32_t* o1 = g_ctx + (((size_t)(b * T_SEQ + row1)) * NH + h) * HD;
#pragma unroll
    for (int ni = 0; ni < 8; ni++) {
        const int d = ni * 8 + 2 * tig;
        uint2 w0, w1;
        w0.x = f2tf32(ctx[ni][0] * inv0);
        w0.y = f2tf32(ctx[ni][1] * inv0);
        w1.x = f2tf32(ctx[ni][2] * inv1);
        w1.y = f2tf32(ctx[ni][3] * inv1);
        *(uint2*)&o0[d] = w0;
        *(uint2*)&o1[d] = w1;
    }
}

// ---------------------------------------------------------------------------
extern "C" void kernel_launch(void* const* d_in, const int* in_sizes, int n_in,
                              void* d_out, int out_size)
{
    const float* x    = (const float*)d_in[0];
    const float* cosT = (const float*)d_in[1];
    const float* sinT = (const float*)d_in[2];
    const float* wq   = (const float*)d_in[3];
    const float* bq   = (const float*)d_in[4];
    const float* wk   = (const float*)d_in[5];
    const float* bk   = (const float*)d_in[6];
    const float* wv   = (const float*)d_in[7];
    const float* bv   = (const float*)d_in[8];
    const float* wo   = (const float*)d_in[9];
    const float* bo   = (const float*)d_in[10];

    float* out  = (float*)d_out;            // (B, T, D)
    float* kout = out + (size_t)8388608;    // (B, KV, T, HD)
    float* vout = out + (size_t)10485760;   // (B, KV, T, HD)

    const int GEMM_SMEM = 4 * TILE_W * 4;    // 81920 B
    const int ATTN_SMEM = 4 * KTILE_W * 4;   // 73728 B
    static bool attr_set = false;
    if (!attr_set) {
        cudaFuncSetAttribute(db_gemm<0>, cudaFuncAttributeMaxDynamicSharedMemorySize, GEMM_SMEM);
        cudaFuncSetAttribute(db_gemm<1>, cudaFuncAttributeMaxDynamicSharedMemorySize, GEMM_SMEM);
        cudaFuncSetAttribute(attn_mma, cudaFuncAttributeMaxDynamicSharedMemorySize, ATTN_SMEM);
        attr_set = true;
    }

    uint32_t* p_xt;  cudaGetSymbolAddress((void**)&p_xt, g_xt);
    uint32_t* p_wq;  cudaGetSymbolAddress((void**)&p_wq, g_wq);
    uint32_t* p_wk;  cudaGetSymbolAddress((void**)&p_wk, g_wk);
    uint32_t* p_wv;  cudaGetSymbolAddress((void**)&p_wv, g_wv);
    uint32_t* p_wo;  cudaGetSymbolAddress((void**)&p_wo, g_wo);
    uint32_t* p_vt;  cudaGetSymbolAddress((void**)&p_vt, g_vt);

    dim3 blk(256);

    // Prep: all fp32 -> tf32 in one launch
    cvt_all<<<18432, 256>>>(x, wq, wk, wv, wo, p_xt, p_wq, p_wk, p_wv, p_wo);

    // Fused QKV projections (+RoPE for Q,K; K also written as tf32 g_kc)
    db_gemm<0><<<dim3(24, 32), blk, GEMM_SMEM>>>(
        p_xt, bq, bk, bv, kout, vout, nullptr, cosT, sinT);

    // V -> transposed tf32
    vtrans<<<dim3(32, 16), blk>>>(vout, p_vt);

    // Attention -> g_ctx (tf32)
    attn_mma<<<dim3(T_SEQ / 128, 2 * NH), blk, ATTN_SMEM>>>();

    // Output projection -> out
    db_gemm<1><<<dim3(16, 32), blk, GEMM_SMEM>>>(
        nullptr, bo, nullptr, nullptr, nullptr, nullptr, out, nullptr, nullptr);
}